// round 1
// baseline (speedup 1.0000x reference)
#include <cuda_runtime.h>
#include <math.h>

#define C_CH 128
#define VN 10
#define NB_TOT 32768           // N*T
#define R_TOT (NB_TOT * VN)    // 327680 rows
#define N3 384
#define HEADS 8
#define DH 16
#define BN_EPS 1e-5f

#define STATS_BLOCKS 512
#define ROWS_PER_STAT (R_TOT / STATS_BLOCKS)   // 640

#define BPC 8                  // batch items per CTA
#define M_TILE (BPC * VN)      // 80 rows
#define THREADS 256

// ---------------- device scratch (no runtime allocation allowed) ----------------
__device__ float g_psum[STATS_BLOCKS][C_CH];
__device__ float g_psumsq[STATS_BLOCKS][C_CH];
__device__ float g_a[C_CH];            // gamma * rstd
__device__ float g_b[C_CH];            // beta - mean * a
__device__ float g_wp[C_CH * N3];      // folded qkv weight: a[k] * w_qkv[k][n]
__device__ float g_bias1[N3];          // sum_k b[k] * w_qkv[k][n]

// ---------------- kernel 1: per-block partial BN stats (deterministic) ----------
__global__ __launch_bounds__(128)
void ga_stats_kernel(const float* __restrict__ x) {
    const int c = threadIdx.x;
    const float* p = x + (size_t)blockIdx.x * ROWS_PER_STAT * C_CH + c;
    float s = 0.f, s2 = 0.f;
#pragma unroll 8
    for (int r = 0; r < ROWS_PER_STAT; ++r) {
        float v = p[(size_t)r * C_CH];
        s += v;
        s2 = fmaf(v, v, s2);
    }
    g_psum[blockIdx.x][c] = s;
    g_psumsq[blockIdx.x][c] = s2;
}

// ---------------- kernel 2: finalize stats -> affine fold coefficients ----------
__global__ __launch_bounds__(128)
void ga_prep_kernel(const float* __restrict__ gamma, const float* __restrict__ beta) {
    const int c = threadIdx.x;
    float s = 0.f, s2 = 0.f;
    for (int b = 0; b < STATS_BLOCKS; ++b) {
        s += g_psum[b][c];
        s2 += g_psumsq[b][c];
    }
    const float invR = 1.0f / (float)R_TOT;
    float mean = s * invR;
    float var = s2 * invR - mean * mean;   // biased variance (matches jnp.var / torch BN)
    float rstd = rsqrtf(var + BN_EPS);
    float a = gamma[c] * rstd;
    g_a[c] = a;
    g_b[c] = beta[c] - mean * a;
}

// ---------------- kernel 3: fold BN into qkv weights ---------------------------
// block n in [0,384): w'[k][n] = a[k]*W[k][n];  bias1[n] = sum_k b[k]*W[k][n]
__global__ __launch_bounds__(128)
void ga_fold_kernel(const float* __restrict__ w_qkv) {
    const int n = blockIdx.x;
    const int k = threadIdx.x;
    float wv = w_qkv[(size_t)k * N3 + n];
    g_wp[(size_t)k * N3 + n] = g_a[k] * wv;
    __shared__ float red[128];
    red[k] = g_b[k] * wv;
    __syncthreads();
    for (int off = 64; off > 0; off >>= 1) {
        if (k < off) red[k] += red[k + off];
        __syncthreads();
    }
    if (k == 0) g_bias1[n] = red[0];
}

// ---------------- kernel 4: fused qkv-gemm + attention + out-proj --------------
struct Smem {
    float xs[128][81];          // x tile transposed [k][m], pad 81 -> conflict-free; reused as attn out
    float qkv[M_TILE][385];     // q|k|v per row (cols 0..383), pad 385
    float ws[2][8][128];        // double-buffered weight k-strips
    float mk[VN][VN];           // graph mask
    float bias1[N3];
    float bout[C_CH];
};

__device__ __forceinline__ void gemm_tile(
    Smem& S, const float (*A)[81], const float* __restrict__ wsrc, int wstride,
    float acc[5][8], int ty5, int tx8, int tid)
{
    // strip 0
    for (int e = tid; e < 1024; e += THREADS)
        S.ws[0][e >> 7][e & 127] = wsrc[(size_t)(e >> 7) * wstride + (e & 127)];
    __syncthreads();

    for (int s = 0; s < 16; ++s) {
        const int cur = s & 1;
        float pre[4];
        if (s < 15) {
#pragma unroll
            for (int j = 0; j < 4; ++j) {
                int e = tid + j * THREADS;
                pre[j] = wsrc[(size_t)((s + 1) * 8 + (e >> 7)) * wstride + (e & 127)];
            }
        }
#pragma unroll
        for (int kk = 0; kk < 8; ++kk) {
            const int k = s * 8 + kk;
            float av[5], bv[8];
#pragma unroll
            for (int r = 0; r < 5; ++r) av[r] = A[k][ty5 + r];
#pragma unroll
            for (int c = 0; c < 8; ++c) bv[c] = S.ws[cur][kk][tx8 + c];
#pragma unroll
            for (int r = 0; r < 5; ++r)
#pragma unroll
                for (int c = 0; c < 8; ++c)
                    acc[r][c] = fmaf(av[r], bv[c], acc[r][c]);
        }
        if (s < 15) {
#pragma unroll
            for (int j = 0; j < 4; ++j) {
                int e = tid + j * THREADS;
                S.ws[cur ^ 1][e >> 7][e & 127] = pre[j];
            }
        }
        __syncthreads();
    }
}

__global__ __launch_bounds__(THREADS, 1)
void ga_main_kernel(const float* __restrict__ x,
                    const float* __restrict__ w_out,
                    const float* __restrict__ b_out,
                    const float* __restrict__ mask,
                    float* __restrict__ out)
{
    extern __shared__ unsigned char smem_raw[];
    Smem& S = *reinterpret_cast<Smem*>(smem_raw);
    const int tid = threadIdx.x;
    const int ty5 = (tid >> 4) * 5;     // 5 rows per thread
    const int tx8 = (tid & 15) * 8;     // 8 cols per thread
    const int row0 = blockIdx.x * M_TILE;

    // preload x tile (transposed), mask, biases
    for (int e = tid; e < M_TILE * C_CH; e += THREADS) {
        int m = e >> 7, k = e & 127;
        S.xs[k][m] = x[(size_t)(row0 + m) * C_CH + k];
    }
    for (int e = tid; e < VN * VN; e += THREADS) S.mk[e / VN][e % VN] = mask[e];
    for (int e = tid; e < N3; e += THREADS) S.bias1[e] = g_bias1[e];
    for (int e = tid; e < C_CH; e += THREADS) S.bout[e] = b_out[e];
    __syncthreads();

    // ---- GEMM1: qkv = x @ w' + bias1 (3 column chunks of 128) ----
    for (int nc = 0; nc < 3; ++nc) {
        float acc[5][8];
#pragma unroll
        for (int r = 0; r < 5; ++r)
#pragma unroll
            for (int c = 0; c < 8; ++c)
                acc[r][c] = S.bias1[nc * 128 + tx8 + c];
        gemm_tile(S, S.xs, g_wp + nc * 128, N3, acc, ty5, tx8, tid);
#pragma unroll
        for (int r = 0; r < 5; ++r)
#pragma unroll
            for (int c = 0; c < 8; ++c)
                S.qkv[ty5 + r][nc * 128 + tx8 + c] = acc[r][c];
    }
    __syncthreads();

    // ---- attention: per (batch, head, row-i) item; writes transposed into S.xs ----
    for (int it = tid; it < BPC * HEADS * VN; it += THREADS) {
        const int b = it / (HEADS * VN);
        const int rem = it - b * (HEADS * VN);
        const int h = rem / VN;
        const int i = rem - h * VN;
        const int h16 = h * DH;
        const int qr = b * VN + i;

        float qv[DH];
#pragma unroll
        for (int d = 0; d < DH; ++d) qv[d] = S.qkv[qr][h16 + d];

        float dots[VN];
        float mx = -1e30f;
#pragma unroll
        for (int j = 0; j < VN; ++j) {
            const float* kr = &S.qkv[b * VN + j][128 + h16];
            float s = 0.f;
#pragma unroll
            for (int d = 0; d < DH; ++d) s = fmaf(qv[d], kr[d], s);
            float v = s * 0.25f * S.mk[i][j];   // scale = DH^-0.5 = 0.25; mask BEFORE softmax
            dots[j] = v;
            mx = fmaxf(mx, v);
        }
        float ssum = 0.f;
#pragma unroll
        for (int j = 0; j < VN; ++j) { dots[j] = expf(dots[j] - mx); ssum += dots[j]; }
        const float inv = 1.0f / ssum;
#pragma unroll
        for (int d = 0; d < DH; ++d) {
            float o = 0.f;
#pragma unroll
            for (int j = 0; j < VN; ++j)
                o = fmaf(dots[j], S.qkv[b * VN + j][256 + h16 + d], o);
            S.xs[h16 + d][qr] = o * inv;        // transposed for GEMM2
        }
    }
    __syncthreads();

    // ---- GEMM2: out = attn_out @ w_out + b_out ----
    {
        float acc[5][8];
#pragma unroll
        for (int r = 0; r < 5; ++r)
#pragma unroll
            for (int c = 0; c < 8; ++c)
                acc[r][c] = S.bout[tx8 + c];
        gemm_tile(S, S.xs, w_out, C_CH, acc, ty5, tx8, tid);
#pragma unroll
        for (int r = 0; r < 5; ++r) {
            size_t o = (size_t)(row0 + ty5 + r) * C_CH + tx8;
            float4 v0 = make_float4(acc[r][0], acc[r][1], acc[r][2], acc[r][3]);
            float4 v1 = make_float4(acc[r][4], acc[r][5], acc[r][6], acc[r][7]);
            *reinterpret_cast<float4*>(&out[o]) = v0;
            *reinterpret_cast<float4*>(&out[o + 4]) = v1;
        }
    }
}

// ---------------- launch ----------------
extern "C" void kernel_launch(void* const* d_in, const int* in_sizes, int n_in,
                              void* d_out, int out_size) {
    (void)in_sizes; (void)n_in; (void)out_size;
    const float* x     = (const float*)d_in[0];
    const float* gamma = (const float*)d_in[1];
    const float* beta  = (const float*)d_in[2];
    const float* w_qkv = (const float*)d_in[3];
    const float* w_out = (const float*)d_in[4];
    const float* b_out = (const float*)d_in[5];
    const float* mask  = (const float*)d_in[6];
    float* out = (float*)d_out;

    cudaFuncSetAttribute(ga_main_kernel,
                         cudaFuncAttributeMaxDynamicSharedMemorySize,
                         (int)sizeof(Smem));

    ga_stats_kernel<<<STATS_BLOCKS, 128>>>(x);
    ga_prep_kernel<<<1, 128>>>(gamma, beta);
    ga_fold_kernel<<<N3, 128>>>(w_qkv);
    ga_main_kernel<<<NB_TOT / BPC, THREADS, sizeof(Smem)>>>(x, w_out, b_out, mask, out);
}

// round 8
// speedup vs baseline: 3.0125x; 3.0125x over previous
#include <cuda_runtime.h>
#include <math.h>
#include <cstdint>

#define C_CH 128
#define VN 10
#define NB_TOT 32768
#define R_TOT (NB_TOT * VN)     // 327680 rows
#define N3 384
#define HEADS 8
#define DH 16
#define BN_EPS 1e-5f

#define STATS_BLOCKS 512
#define ROWS_PER_STAT (R_TOT / STATS_BLOCKS)

#define BPC 6
#define MROWS (BPC * VN)        // 60 valid rows, padded to 64
#define MPAD 64
#define THREADS 256
#define GRID_MAIN ((NB_TOT + BPC - 1) / BPC)   // 5462

// smem layout (byte offsets)
#define XS_OFF    0u                       // [64][132] floats = 33792 B (x tile, later P)
#define WT_OFF    33792u                   // 2 x [64][136] floats = 69632 B
#define WT_BUF_B  34816u
#define QKV_OFF   103424u                  // [64][385] floats = 98560 B
#define BIAS1_OFF 201984u                  // 384 f
#define BOUT_OFF  203520u                  // 128 f
#define MASK_OFF  204032u                  // 100 f
#define SMEM_TOTAL 204432u

// ---------------- device scratch ----------------
__device__ float g_psum[STATS_BLOCKS][C_CH];
__device__ float g_psumsq[STATS_BLOCKS][C_CH];
__device__ float g_a[C_CH];
__device__ float g_b[C_CH];
__device__ float g_bias1[N3];
__device__ float g_w1t[3 * 16384];   // [chunk][k][n] tf32-rounded folded W1
__device__ float g_w2t[16384];       // [k][n]       tf32-rounded W2

// ---------------- helpers ----------------
__device__ __forceinline__ uint32_t smem_u32(const void* p) {
    uint32_t a;
    asm("{ .reg .u64 t; cvta.to.shared.u64 t, %1; cvt.u32.u64 %0, t; }" : "=r"(a) : "l"(p));
    return a;
}
__device__ __forceinline__ float tf32_round(float f) {
    uint32_t r;
    asm("cvt.rna.tf32.f32 %0, %1;" : "=r"(r) : "f"(f));
    return __uint_as_float(r);
}
#define CP_ASYNC16(dst, src) \
    asm volatile("cp.async.ca.shared.global [%0], [%1], 16;" :: "r"(dst), "l"(src) : "memory")
#define CP_COMMIT() asm volatile("cp.async.commit_group;" ::: "memory")
#define CP_WAIT(n)  asm volatile("cp.async.wait_group %0;" :: "n"(n) : "memory")

__device__ __forceinline__ void mma8(float* d, const uint32_t* a, uint32_t b0, uint32_t b1) {
    asm volatile(
        "mma.sync.aligned.m16n8k8.row.col.f32.tf32.tf32.f32 "
        "{%0,%1,%2,%3},{%4,%5,%6,%7},{%8,%9},{%0,%1,%2,%3};"
        : "+f"(d[0]), "+f"(d[1]), "+f"(d[2]), "+f"(d[3])
        : "r"(a[0]), "r"(a[1]), "r"(a[2]), "r"(a[3]), "r"(b0), "r"(b1));
}

// ---------------- kernel 1: BN partial stats ----------------
__global__ __launch_bounds__(128)
void ga_stats_kernel(const float* __restrict__ x) {
    const int c = threadIdx.x;
    const float* p = x + (size_t)blockIdx.x * ROWS_PER_STAT * C_CH + c;
    float s = 0.f, s2 = 0.f;
#pragma unroll 8
    for (int r = 0; r < ROWS_PER_STAT; ++r) {
        float v = p[(size_t)r * C_CH];
        s += v;
        s2 = fmaf(v, v, s2);
    }
    g_psum[blockIdx.x][c] = s;
    g_psumsq[blockIdx.x][c] = s2;
}

// ---------------- kernel 2: finalize stats ----------------
__global__ __launch_bounds__(128)
void ga_prep_kernel(const float* __restrict__ gamma, const float* __restrict__ beta) {
    const int c = threadIdx.x;
    float s = 0.f, s2 = 0.f;
    for (int b = 0; b < STATS_BLOCKS; ++b) { s += g_psum[b][c]; s2 += g_psumsq[b][c]; }
    const float invR = 1.0f / (float)R_TOT;
    float mean = s * invR;
    float var = s2 * invR - mean * mean;
    float rstd = rsqrtf(var + BN_EPS);
    float a = gamma[c] * rstd;
    g_a[c] = a;
    g_b[c] = beta[c] - mean * a;
}

// ---------------- kernel 3a: fold BN into W1 (transposed, tf32-rounded) + bias1 ----
__global__ __launch_bounds__(128)
void ga_fold1_kernel(const float* __restrict__ w_qkv) {
    const int n3 = blockIdx.x;      // 0..383
    const int k = threadIdx.x;      // 0..127
    float wv = w_qkv[(size_t)k * N3 + n3];
    g_w1t[(n3 >> 7) * 16384 + k * 128 + (n3 & 127)] = tf32_round(g_a[k] * wv);
    __shared__ float red[128];
    red[k] = g_b[k] * wv;
    __syncthreads();
    for (int off = 64; off > 0; off >>= 1) {
        if (k < off) red[k] += red[k + off];
        __syncthreads();
    }
    if (k == 0) g_bias1[n3] = red[0];
}

// ---------------- kernel 3b: W2 tf32-rounded ----------------
__global__ __launch_bounds__(128)
void ga_fold2_kernel(const float* __restrict__ w_out) {
    const int k = blockIdx.x;       // 0..127 (inner)
    const int n = threadIdx.x;      // 0..127 (out ch)
    g_w2t[k * 128 + n] = tf32_round(w_out[(size_t)k * C_CH + n]);
}

// ---------------- main fused kernel ----------------
__device__ __forceinline__ void issue_strip(int s, char* smem, int tid) {
    const float* src = (s < 6) ? (g_w1t + (s >> 1) * 16384 + (s & 1) * 8192)
                               : (g_w2t + (s & 1) * 8192);
    const uint32_t dstbase = smem_u32(smem + WT_OFF + (uint32_t)(s & 1) * WT_BUF_B);
#pragma unroll
    for (int j = 0; j < 8; ++j) {
        const int u = tid + j * THREADS;          // 2048 units of 16B
        const int k = u >> 5, gq = u & 31;
        const uint32_t dst = dstbase + (uint32_t)(k * 136 + gq * 4) * 4u;
        CP_ASYNC16(dst, src + u * 4);
    }
}

__device__ __forceinline__ void compute_half(
    const uint32_t* __restrict__ xsu, const uint32_t* __restrict__ wtu,
    int h, int wm, int wn, int g, int tig, float acc[2][4][4])
{
#pragma unroll
    for (int ks = 0; ks < 8; ++ks) {
        const int kg = h * 64 + ks * 8;
        uint32_t a[2][4];
#pragma unroll
        for (int mt = 0; mt < 2; ++mt) {
            const int row = wm * 32 + mt * 16 + g;
            a[mt][0] = xsu[row * 132 + kg + tig];
            a[mt][1] = xsu[(row + 8) * 132 + kg + tig];
            a[mt][2] = xsu[row * 132 + kg + tig + 4];
            a[mt][3] = xsu[(row + 8) * 132 + kg + tig + 4];
        }
#pragma unroll
        for (int nt = 0; nt < 4; ++nt) {
            const int n = wn * 32 + nt * 8 + g;
            const uint32_t b0 = wtu[(ks * 8 + tig) * 136 + n];
            const uint32_t b1 = wtu[(ks * 8 + tig + 4) * 136 + n];
            mma8(acc[0][nt], a[0], b0, b1);
            mma8(acc[1][nt], a[1], b0, b1);
        }
    }
}

__global__ __launch_bounds__(THREADS, 1)
void ga_main_kernel(const float* __restrict__ x,
                    const float* __restrict__ b_out,
                    const float* __restrict__ mask,
                    float* __restrict__ out)
{
    extern __shared__ char smem[];
    float* xs = (float*)(smem + XS_OFF);
    float* qkv = (float*)(smem + QKV_OFF);
    float* bias1s = (float*)(smem + BIAS1_OFF);
    float* bouts = (float*)(smem + BOUT_OFF);
    float* mk = (float*)(smem + MASK_OFF);
    uint32_t* xsu = (uint32_t*)xs;
    const uint32_t* wtu0 = (const uint32_t*)(smem + WT_OFF);
    const uint32_t* wtu1 = (const uint32_t*)(smem + WT_OFF + WT_BUF_B);

    const int tid = threadIdx.x;
    const int lane = tid & 31;
    const int wid = tid >> 5;
    const int wm = wid & 1;        // 2 M-strips of 32
    const int wn = wid >> 1;       // 4 N-strips of 32
    const int g = lane >> 2;
    const int tig = lane & 3;

    const int row0 = blockIdx.x * MROWS;
    const int valid_rows = min(MROWS, R_TOT - row0);
    const int valid_items = min(BPC, NB_TOT - blockIdx.x * BPC);

    // prefetch weight strips 0,1 (gemm1 chunk0)
    issue_strip(0, smem, tid); CP_COMMIT();
    issue_strip(1, smem, tid); CP_COMMIT();

    // constants
    for (int e = tid; e < N3; e += THREADS) bias1s[e] = g_bias1[e];
    for (int e = tid; e < C_CH; e += THREADS) bouts[e] = b_out[e];
    for (int e = tid; e < VN * VN; e += THREADS) mk[e] = mask[e];

    // x tile -> xs (tf32-rounded), pad rows zeroed
    {
        const float4* xv = reinterpret_cast<const float4*>(x);
#pragma unroll
        for (int j = 0; j < 8; ++j) {
            const int idx = tid + j * THREADS;       // 2048 = 64 rows x 32 groups
            const int m = idx >> 5, gq = idx & 31;
            float4 v = make_float4(0.f, 0.f, 0.f, 0.f);
            if (m < valid_rows) v = xv[(size_t)(row0 + m) * 32 + gq];
            v.x = tf32_round(v.x); v.y = tf32_round(v.y);
            v.z = tf32_round(v.z); v.w = tf32_round(v.w);
            *reinterpret_cast<float4*>(&xs[m * 132 + gq * 4]) = v;
        }
    }
    __syncthreads();

    // ---- GEMM1: qkv = x @ W1' + bias1, 3 N-chunks of 128 ----
#pragma unroll 1
    for (int c = 0; c < 3; ++c) {
        float acc[2][4][4];
#pragma unroll
        for (int nt = 0; nt < 4; ++nt) {
            const int col = c * 128 + wn * 32 + nt * 8 + tig * 2;
            const float bz0 = bias1s[col], bz1 = bias1s[col + 1];
#pragma unroll
            for (int mt = 0; mt < 2; ++mt) {
                acc[mt][nt][0] = bz0; acc[mt][nt][1] = bz1;
                acc[mt][nt][2] = bz0; acc[mt][nt][3] = bz1;
            }
        }
#pragma unroll 1
        for (int h = 0; h < 2; ++h) {
            const int s = c * 2 + h;
            CP_WAIT(1);
            __syncthreads();
            compute_half(xsu, (s & 1) ? wtu1 : wtu0, h, wm, wn, g, tig, acc);
            __syncthreads();
            issue_strip(s + 2, smem, tid); CP_COMMIT();
        }
        // store acc -> qkv
#pragma unroll
        for (int mt = 0; mt < 2; ++mt) {
            const int row = wm * 32 + mt * 16 + g;
#pragma unroll
            for (int nt = 0; nt < 4; ++nt) {
                const int col = c * 128 + wn * 32 + nt * 8 + tig * 2;
                qkv[row * 385 + col]           = acc[mt][nt][0];
                qkv[row * 385 + col + 1]       = acc[mt][nt][1];
                qkv[(row + 8) * 385 + col]     = acc[mt][nt][2];
                qkv[(row + 8) * 385 + col + 1] = acc[mt][nt][3];
            }
        }
    }
    __syncthreads();

    // ---- attention (fp32, scalar); writes P (tf32) into xs ----
    for (int it = tid; it < BPC * HEADS * VN; it += THREADS) {
        const int b = it / (HEADS * VN);
        const int rem = it - b * (HEADS * VN);
        const int h = rem / VN;
        const int i = rem - h * VN;
        if (b < valid_items) {
            const int h16 = h * DH;
            const int ri = b * VN + i;
            float qv[DH];
#pragma unroll
            for (int d = 0; d < DH; ++d) qv[d] = qkv[ri * 385 + h16 + d];
            float dots[VN];
            float mx = -1e30f;
#pragma unroll
            for (int j = 0; j < VN; ++j) {
                const float* kr = &qkv[(b * VN + j) * 385 + 128 + h16];
                float s = 0.f;
#pragma unroll
                for (int d = 0; d < DH; ++d) s = fmaf(qv[d], kr[d], s);
                float v = s * 0.25f * mk[i * VN + j];
                dots[j] = v;
                mx = fmaxf(mx, v);
            }
            float ssum = 0.f;
#pragma unroll
            for (int j = 0; j < VN; ++j) { dots[j] = __expf(dots[j] - mx); ssum += dots[j]; }
            const float inv = 1.0f / ssum;
#pragma unroll
            for (int d = 0; d < DH; ++d) {
                float o = 0.f;
#pragma unroll
                for (int j = 0; j < VN; ++j)
                    o = fmaf(dots[j], qkv[(b * VN + j) * 385 + 256 + h16 + d], o);
                xs[ri * 132 + h16 + d] = tf32_round(o * inv);
            }
        }
    }
    __syncthreads();

    // ---- GEMM2: out = P @ W2 + b_out (W2 strips 6,7 already prefetched) ----
    CP_WAIT(0);
    __syncthreads();
    {
        float acc[2][4][4];
#pragma unroll
        for (int nt = 0; nt < 4; ++nt) {
            const int col = wn * 32 + nt * 8 + tig * 2;
            const float bz0 = bouts[col], bz1 = bouts[col + 1];
#pragma unroll
            for (int mt = 0; mt < 2; ++mt) {
                acc[mt][nt][0] = bz0; acc[mt][nt][1] = bz1;
                acc[mt][nt][2] = bz0; acc[mt][nt][3] = bz1;
            }
        }
        compute_half(xsu, wtu0, 0, wm, wn, g, tig, acc);
        compute_half(xsu, wtu1, 1, wm, wn, g, tig, acc);

#pragma unroll
        for (int mt = 0; mt < 2; ++mt) {
            const int row = wm * 32 + mt * 16 + g;
#pragma unroll
            for (int nt = 0; nt < 4; ++nt) {
                const int col = wn * 32 + nt * 8 + tig * 2;
                if (row < valid_rows) {
                    float2 v = make_float2(acc[mt][nt][0], acc[mt][nt][1]);
                    *reinterpret_cast<float2*>(&out[(size_t)(row0 + row) * C_CH + col]) = v;
                }
                if (row + 8 < valid_rows) {
                    float2 v = make_float2(acc[mt][nt][2], acc[mt][nt][3]);
                    *reinterpret_cast<float2*>(&out[(size_t)(row0 + row + 8) * C_CH + col]) = v;
                }
            }
        }
    }
}

// ---------------- launch ----------------
extern "C" void kernel_launch(void* const* d_in, const int* in_sizes, int n_in,
                              void* d_out, int out_size) {
    (void)in_sizes; (void)n_in; (void)out_size;
    const float* x     = (const float*)d_in[0];
    const float* gamma = (const float*)d_in[1];
    const float* beta  = (const float*)d_in[2];
    const float* w_qkv = (const float*)d_in[3];
    const float* w_out = (const float*)d_in[4];
    const float* b_out = (const float*)d_in[5];
    const float* mask  = (const float*)d_in[6];
    float* out = (float*)d_out;

    cudaFuncSetAttribute(ga_main_kernel,
                         cudaFuncAttributeMaxDynamicSharedMemorySize,
                         (int)SMEM_TOTAL);

    ga_stats_kernel<<<STATS_BLOCKS, 128>>>(x);
    ga_prep_kernel<<<1, 128>>>(gamma, beta);
    ga_fold1_kernel<<<N3, 128>>>(w_qkv);
    ga_fold2_kernel<<<C_CH, 128>>>(w_out);
    ga_main_kernel<<<GRID_MAIN, THREADS, SMEM_TOTAL>>>(x, b_out, mask, out);
}